// round 1
// baseline (speedup 1.0000x reference)
#include <cuda_runtime.h>

// DCN cross: x_l = x_0 * (x_l . W[i]) + b_lin[i] + bias[i] + x_l, L=4 layers.
// B=8192 rows, D=256. One warp per row; row held in registers as 2x float4
// per lane. HBM-bound: 8MB read + 8MB write is the only mandatory traffic.

constexpr int D = 256;
constexpr int L = 4;

__global__ __launch_bounds__(256, 8)
void cross_kernel(const float* __restrict__ x,
                  const float* __restrict__ W,
                  const float* __restrict__ b_lin,
                  const float* __restrict__ bias,
                  float* __restrict__ out,
                  int B)
{
    const int warp_id = (blockIdx.x * blockDim.x + threadIdx.x) >> 5;
    const int lane    = threadIdx.x & 31;
    if (warp_id >= B) return;

    // Each lane owns elements [4*lane .. 4*lane+3] and [128+4*lane .. 128+4*lane+3]
    const float4* xrow = reinterpret_cast<const float4*>(x + (size_t)warp_id * D);
    float4 x0a = xrow[lane];
    float4 x0b = xrow[lane + 32];
    float4 xla = x0a;
    float4 xlb = x0b;

    #pragma unroll
    for (int i = 0; i < L; ++i) {
        const float4* Wr = reinterpret_cast<const float4*>(W + i * D);
        float4 w0 = Wr[lane];
        float4 w1 = Wr[lane + 32];

        // local partial dot
        float s = xla.x * w0.x;
        s = fmaf(xla.y, w0.y, s);
        s = fmaf(xla.z, w0.z, s);
        s = fmaf(xla.w, w0.w, s);
        s = fmaf(xlb.x, w1.x, s);
        s = fmaf(xlb.y, w1.y, s);
        s = fmaf(xlb.z, w1.z, s);
        s = fmaf(xlb.w, w1.w, s);

        // warp butterfly reduce -> full dot in every lane
        #pragma unroll
        for (int o = 16; o > 0; o >>= 1)
            s += __shfl_xor_sync(0xffffffffu, s, o);

        const float4* Br = reinterpret_cast<const float4*>(bias + i * D);
        float4 b0 = Br[lane];
        float4 b1 = Br[lane + 32];
        const float bl = b_lin[i];

        // x_l = x_0 * s + (bl + bias) + x_l
        xla.x = fmaf(x0a.x, s, bl + b0.x + xla.x);
        xla.y = fmaf(x0a.y, s, bl + b0.y + xla.y);
        xla.z = fmaf(x0a.z, s, bl + b0.z + xla.z);
        xla.w = fmaf(x0a.w, s, bl + b0.w + xla.w);
        xlb.x = fmaf(x0b.x, s, bl + b1.x + xlb.x);
        xlb.y = fmaf(x0b.y, s, bl + b1.y + xlb.y);
        xlb.z = fmaf(x0b.z, s, bl + b1.z + xlb.z);
        xlb.w = fmaf(x0b.w, s, bl + b1.w + xlb.w);
    }

    float4* orow = reinterpret_cast<float4*>(out + (size_t)warp_id * D);
    orow[lane]      = xla;
    orow[lane + 32] = xlb;
}

extern "C" void kernel_launch(void* const* d_in, const int* in_sizes, int n_in,
                              void* d_out, int out_size)
{
    const float* x     = (const float*)d_in[0];
    const float* W     = (const float*)d_in[1];
    const float* b_lin = (const float*)d_in[2];
    const float* bias  = (const float*)d_in[3];
    float* out         = (float*)d_out;

    const int B = in_sizes[0] / D;           // 8192
    const int threads = 256;                 // 8 warps = 8 rows per block
    const int rows_per_block = threads / 32;
    const int blocks = (B + rows_per_block - 1) / rows_per_block;

    cross_kernel<<<blocks, threads>>>(x, W, b_lin, bias, out, B);
}

// round 3
// speedup vs baseline: 1.1971x; 1.1971x over previous
#include <cuda_runtime.h>

// DCN cross, B=8192, D=256, L=4. Latency-bound fix:
//  - 4 rows per warp: independent dot/reduce/update chains give ILP that hides
//    SHFL latency; front-batched LDG.128 raises MLP.
//  - shfl.xor butterfly reduction (redux.f32 unsupported on sm_103).

constexpr int D = 256;
constexpr int L = 4;
constexpr int R = 4;   // rows per warp

__global__ __launch_bounds__(256)
void cross_kernel(const float* __restrict__ x,
                  const float* __restrict__ W,
                  const float* __restrict__ b_lin,
                  const float* __restrict__ bias,
                  float* __restrict__ out,
                  int B)
{
    const int warp_id = (blockIdx.x * blockDim.x + threadIdx.x) >> 5;
    const int lane    = threadIdx.x & 31;
    const int row0    = warp_id * R;
    if (row0 >= B) return;

    float4 x0a[R], x0b[R], xla[R], xlb[R];

    // Front-batched loads: 8 independent LDG.128 per lane -> high MLP
    #pragma unroll
    for (int r = 0; r < R; ++r) {
        const float4* xrow = reinterpret_cast<const float4*>(x + (size_t)(row0 + r) * D);
        x0a[r] = xrow[lane];
        x0b[r] = xrow[lane + 32];
    }
    #pragma unroll
    for (int r = 0; r < R; ++r) { xla[r] = x0a[r]; xlb[r] = x0b[r]; }

    #pragma unroll
    for (int i = 0; i < L; ++i) {
        const float4* Wr = reinterpret_cast<const float4*>(W + i * D);
        const float4 w0 = Wr[lane];
        const float4 w1 = Wr[lane + 32];

        float s[R];
        #pragma unroll
        for (int r = 0; r < R; ++r) {
            float t = xla[r].x * w0.x;
            t = fmaf(xla[r].y, w0.y, t);
            t = fmaf(xla[r].z, w0.z, t);
            t = fmaf(xla[r].w, w0.w, t);
            t = fmaf(xlb[r].x, w1.x, t);
            t = fmaf(xlb[r].y, w1.y, t);
            t = fmaf(xlb[r].z, w1.z, t);
            t = fmaf(xlb[r].w, w1.w, t);
            s[r] = t;
        }

        // 4 independent butterfly reductions — interleaved by the scheduler,
        // so the 5-step SHFL ladder latency is paid roughly once, not 4x.
        #pragma unroll
        for (int o = 16; o > 0; o >>= 1) {
            #pragma unroll
            for (int r = 0; r < R; ++r)
                s[r] += __shfl_xor_sync(0xffffffffu, s[r], o);
        }

        const float4* Br = reinterpret_cast<const float4*>(bias + i * D);
        const float4 b0 = Br[lane];
        const float4 b1 = Br[lane + 32];
        const float bl = b_lin[i];

        #pragma unroll
        for (int r = 0; r < R; ++r) {
            xla[r].x = fmaf(x0a[r].x, s[r], bl + b0.x + xla[r].x);
            xla[r].y = fmaf(x0a[r].y, s[r], bl + b0.y + xla[r].y);
            xla[r].z = fmaf(x0a[r].z, s[r], bl + b0.z + xla[r].z);
            xla[r].w = fmaf(x0a[r].w, s[r], bl + b0.w + xla[r].w);
            xlb[r].x = fmaf(x0b[r].x, s[r], bl + b1.x + xlb[r].x);
            xlb[r].y = fmaf(x0b[r].y, s[r], bl + b1.y + xlb[r].y);
            xlb[r].z = fmaf(x0b[r].z, s[r], bl + b1.z + xlb[r].z);
            xlb[r].w = fmaf(x0b[r].w, s[r], bl + b1.w + xlb[r].w);
        }
    }

    #pragma unroll
    for (int r = 0; r < R; ++r) {
        float4* orow = reinterpret_cast<float4*>(out + (size_t)(row0 + r) * D);
        orow[lane]      = xla[r];
        orow[lane + 32] = xlb[r];
    }
}

extern "C" void kernel_launch(void* const* d_in, const int* in_sizes, int n_in,
                              void* d_out, int out_size)
{
    const float* x     = (const float*)d_in[0];
    const float* W     = (const float*)d_in[1];
    const float* b_lin = (const float*)d_in[2];
    const float* bias  = (const float*)d_in[3];
    float* out         = (float*)d_out;

    const int B = in_sizes[0] / D;                 // 8192
    const int threads = 256;                       // 8 warps/block
    const int rows_per_block = (threads / 32) * R; // 32 rows/block
    const int blocks = (B + rows_per_block - 1) / rows_per_block;  // 256

    cross_kernel<<<blocks, threads>>>(x, W, b_lin, bias, out, B);
}